// round 10
// baseline (speedup 1.0000x reference)
#include <cuda_runtime.h>
#include <math.h>
#include <stdint.h>

// Problem shape (fixed by the reference setup_inputs)
#define BB 32
#define PP 8732
#define CC 81
#define NPRI (BB * PP)             // 279424 rows
#define TROWS 16                   // rows per tile
#define NTILES (NPRI / TROWS)      // 17464 (exact)
#define TILE_FLOATS (TROWS * CC)   // 1296
#define TILE_F4 (TILE_FLOATS / 4)  // 324
#define LAB_F4 (TROWS / 4)         // 4 (labels staged as int4)
#define STAGE_F4 (TILE_F4 + LAB_F4)// 328 float4 = 5248 B
#define STAGES 4                   // 20992 B of stages
#define LOOKAHEAD 3
#define TPB 256
#define G 1024                     // 32*32: single wave at 7 blocks/SM on 148 SMs
#define BPB (G / BB)               // 32 blocks per batch (loc partials)

// Scratch (static __device__ — no allocation allowed)
__device__ float g_ce[NPRI];       // per-prior CE
__device__ float g_bg[NPRI];       // per-prior bg loss, -inf on positives
__device__ float g_cepart[G];      // per-block partial CE sum
__device__ float g_sl1part[G];     // per-block smooth-L1 partial
__device__ int   g_nppart[G];      // per-block positive-count partial
__device__ int   g_npos[BB];       // per-batch positive count (finisher-built)
__device__ int   g_ctr;            // finisher counter (zero-init, reset each call)

__device__ __forceinline__ void cp16(uint32_t dst_smem, const void* src) {
    asm volatile("cp.async.cg.shared.global [%0], [%1], 16;" :: "r"(dst_smem), "l"(src));
}
__device__ __forceinline__ void cp_commit() {
    asm volatile("cp.async.commit_group;");
}
template <int N> __device__ __forceinline__ void cp_wait() {
    asm volatile("cp.async.wait_group %0;" :: "n"(N));
}

// ---------------------------------------------------------------------------
// k1: whole problem, one kernel, G=1024 persistent blocks (single wave,
// 7 blocks/SM via launch_bounds reg target).
//  1) cp.async prologue: LOOKAHEAD conf tiles in flight
//  2) loc slice (~273 priors/block; slice bounds align with batch bounds)
//  3) conf pipeline: wait<2>/barrier/compute/issue t+3/commit.
//     Tile = 16 rows; warp = 2 rows, 16 lanes/row, 5 exps/lane.
//  4) last block finalizes; general mining fallback reads bg via L2.
// ---------------------------------------------------------------------------
__global__ void __launch_bounds__(TPB, 7) k1(const float* __restrict__ conf,
                                             const float* __restrict__ pred,
                                             const float* __restrict__ gt,
                                             const int* __restrict__ labels,
                                             float* __restrict__ out) {
    __shared__ float4 stg[STAGES][STAGE_F4];   // 20992 B
    __shared__ float  sred[TPB];
    __shared__ int    sint[TPB];
    __shared__ int    s_last;
    __shared__ int    s_fast;
    __shared__ float  s_cs;
    const int bx   = blockIdx.x;
    const int tid  = threadIdx.x;
    const int lane = tid & 31;
    const int wid  = tid >> 5;
    const unsigned FULL = 0xffffffffu;

    const int start = (int)(((long long)bx * NTILES) / G);
    const int end   = (int)(((long long)(bx + 1) * NTILES) / G);
    const float4* conf4 = reinterpret_cast<const float4*>(conf);
    const int4*   lab4  = reinterpret_cast<const int4*>(labels);

    auto issue = [&](int t, int s) {
        uint32_t sbase = (uint32_t)__cvta_generic_to_shared(&stg[s][0]);
        #pragma unroll
        for (int i = tid; i < STAGE_F4; i += TPB) {   // <= 2 iterations
            const void* src = (i < TILE_F4)
                ? (const void*)(conf4 + (size_t)t * TILE_F4 + i)
                : (const void*)(lab4 + (size_t)t * LAB_F4 + (i - TILE_F4));
            cp16(sbase + (uint32_t)i * 16u, src);
        }
    };

    // ---- 1) prologue: LOOKAHEAD tiles in flight ----
    #pragma unroll
    for (int i = 0; i < LOOKAHEAD; i++) {
        if (start + i < end) issue(start + i, i);
        cp_commit();                       // always commit (group-count invariant)
    }

    // ---- 2) loc slice (overlaps the fills) ----
    {
        const int p0 = (int)(((long long)bx * NPRI) / G);
        const int p1 = (int)(((long long)(bx + 1) * NPRI) / G);
        int   np  = 0;
        float sl1 = 0.f;
        for (int p = p0 + tid; p < p1; p += TPB) {
            const int lab = labels[p];
            if (lab > 0) {
                np++;
                const float4 pv = *reinterpret_cast<const float4*>(pred + (size_t)p * 4);
                const float4 gv = *reinterpret_cast<const float4*>(gt   + (size_t)p * 4);
                float d, ad;
                d = pv.x - gv.x; ad = fabsf(d); sl1 += (ad < 1.f) ? 0.5f * d * d : ad - 0.5f;
                d = pv.y - gv.y; ad = fabsf(d); sl1 += (ad < 1.f) ? 0.5f * d * d : ad - 0.5f;
                d = pv.z - gv.z; ad = fabsf(d); sl1 += (ad < 1.f) ? 0.5f * d * d : ad - 0.5f;
                d = pv.w - gv.w; ad = fabsf(d); sl1 += (ad < 1.f) ? 0.5f * d * d : ad - 0.5f;
            }
        }
        sred[tid] = sl1;
        sint[tid] = np;
        __syncthreads();
        for (int st = TPB / 2; st > 0; st >>= 1) {
            if (tid < st) { sred[tid] += sred[tid + st]; sint[tid] += sint[tid + st]; }
            __syncthreads();
        }
        if (tid == 0) { g_sl1part[bx] = sred[0]; g_nppart[bx] = sint[0]; }
    }

    // ---- 3) conf pipeline ----
    float ce_acc = 0.f;
    const int row = (wid << 1) + (lane >> 4);  // 2 rows per warp
    const int sub = lane & 15;                 // 16 workers per row

    for (int t = start; t < end; t++) {
        const int s = (t - start) & (STAGES - 1);
        cp_wait<LOOKAHEAD - 1>();  // groups through tile t complete
        __syncthreads();           // visible block-wide; stage t-1 fully consumed

        const float* sp   = reinterpret_cast<const float*>(&stg[s][0]);
        const int*   slab = reinterpret_cast<const int*>(sp + TILE_FLOATS);
        const float* rp   = sp + row * CC;

        // 5 cols per lane (sub, sub+16, ..., sub+64), col 80 on sub==0
        float a0 = __expf(rp[sub])      + __expf(rp[sub + 32]);
        float a1 = __expf(rp[sub + 16]) + __expf(rp[sub + 48]);
        a0 += __expf(rp[sub + 64]);
        float a = a0 + a1;
        const int lab = slab[row];
        if (sub == 0) a += __expf(rp[80]);
        a += __shfl_xor_sync(FULL, a, 1);
        a += __shfl_xor_sync(FULL, a, 2);
        a += __shfl_xor_sync(FULL, a, 4);
        a += __shfl_xor_sync(FULL, a, 8);
        if (sub == 0) {                 // lanes 0 and 16: one per row
            const float lse  = __logf(a);
            const float pick = rp[lab];
            const float x0   = rp[0];
            const float ce   = lse - pick;
            const int   rg   = t * TROWS + row;
            g_ce[rg] = ce;
            g_bg[rg] = (lab > 0) ? -INFINITY : (lse - x0);
            ce_acc += ce;
        }
        // issue tile t+LOOKAHEAD into the stage that held tile t-1
        const int tn = t + LOOKAHEAD;
        if (tn < end) issue(tn, (tn - start) & (STAGES - 1));
        cp_commit();               // always commit (keeps wait<2> aligned to tile t)
    }
    cp_wait<0>();

    // per-block CE partial (static tile assignment -> deterministic)
    sred[tid] = ce_acc;
    __syncthreads();
    for (int st = TPB / 2; st > 0; st >>= 1) {
        if (tid < st) sred[tid] += sred[tid + st];
        __syncthreads();
    }
    if (tid == 0) g_cepart[bx] = sred[0];

    // ---- 4) finisher (last block of the grid) ----
    if (tid == 0) {
        __threadfence();
        s_last = (atomicAdd(&g_ctr, 1) == G - 1);
    }
    __syncthreads();
    if (!s_last) return;

    // rebuild per-batch npos: batch b == blocks [32b, 32b+32) exactly
    int slow = 0;
    if (tid < BB) {
        int np = 0;
        #pragma unroll
        for (int i = 0; i < BPB; i++) np += g_nppart[tid * BPB + i];
        g_npos[tid] = np;
        slow = ((long long)np * 3 < (long long)PP);
    }
    const unsigned slowmask = __ballot_sync(FULL, slow);  // warp 0's is meaningful
    if (tid == 0) s_fast = (slowmask == 0u);
    __syncthreads();

    if (s_fast) {
        // total CE = sum of all block partials (fixed order -> deterministic)
        float cs = 0.f;
        for (int i = tid; i < G; i += TPB) cs += g_cepart[i];
        sred[tid] = cs;
        __syncthreads();
        for (int st = TPB / 2; st > 0; st >>= 1) {
            if (tid < st) sred[tid] += sred[tid + st];
            __syncthreads();
        }
        if (tid == 0) s_cs = sred[0];
        __syncthreads();
    } else {
        // general path (correctness fallback; O(P^2) mining, bg via L2)
        if (tid == 0) s_cs = 0.f;
        __syncthreads();
        for (int b = 0; b < BB; b++) {
            const int np = g_npos[b];
            const long long num_neg = (long long)np * 3;
            const float* ce = g_ce + b * PP;
            const float* bg = g_bg + b * PP;
            float acc = 0.f;
            if (num_neg >= PP) {
                for (int p = tid; p < PP; p += TPB) acc += ce[p];
            } else {
                for (int p = tid; p < PP; p += TPB) {
                    const float v = bg[p];
                    bool sel;
                    if (v == -INFINITY) {
                        sel = true;  // positive: always selected
                    } else {
                        int rank = 0;
                        for (int j = 0; j < PP; j++) {
                            const float w = bg[j];
                            rank += (w > v) || (w == v && j < p);  // stable-argsort tiebreak
                        }
                        sel = (rank < num_neg);
                    }
                    if (sel) acc += ce[p];
                }
            }
            sred[tid] = acc;
            __syncthreads();
            for (int st = TPB / 2; st > 0; st >>= 1) {
                if (tid < st) sred[tid] += sred[tid + st];
                __syncthreads();
            }
            if (tid == 0) s_cs += sred[0];  // fixed batch order -> deterministic
            __syncthreads();
        }
    }

    // common tail: total smooth-L1 + total npos, write out[]
    float sl = 0.f;
    for (int i = tid; i < G; i += TPB) sl += g_sl1part[i];
    sred[tid] = sl;
    __syncthreads();
    for (int st = TPB / 2; st > 0; st >>= 1) {
        if (tid < st) sred[tid] += sred[tid + st];
        __syncthreads();
    }
    if (tid < 32) {  // BB == 32
        int np = g_npos[tid];
        #pragma unroll
        for (int o = 16; o > 0; o >>= 1) np += __shfl_xor_sync(FULL, np, o);
        if (tid == 0) {
            const float inv = 1.f / (float)np;
            out[0] = sred[0] * inv;
            out[1] = s_cs * inv;
            g_ctr = 0;   // reset for next replay
        }
    }
}

// ---------------------------------------------------------------------------
extern "C" void kernel_launch(void* const* d_in, const int* in_sizes, int n_in,
                              void* d_out, int out_size) {
    const float* conf   = (const float*)d_in[0];   // (32, 8732, 81) f32
    const float* pred   = (const float*)d_in[1];   // (32, 8732, 4)  f32
    const int*   labels = (const int*)d_in[2];     // (32, 8732)     i32
    const float* gt     = (const float*)d_in[3];   // (32, 8732, 4)  f32
    float* out = (float*)d_out;                    // 2 floats

    k1<<<G, TPB>>>(conf, pred, gt, labels, out);
}

// round 12
// speedup vs baseline: 1.0656x; 1.0656x over previous
#include <cuda_runtime.h>
#include <math.h>
#include <stdint.h>

// Problem shape (fixed by the reference setup_inputs)
#define BB 32
#define PP 8732
#define CC 81
#define NPRI (BB * PP)             // 279424 rows
#define TROWS 64                   // rows per tile
#define NTILES (NPRI / TROWS)      // 4366 (exact)
#define TILE_FLOATS (TROWS * CC)   // 5184
#define TILE_F4 (TILE_FLOATS / 4)  // 1296
#define LAB_F4 (TROWS / 4)         // 16 (labels staged as int4)
#define STAGE_F4 (TILE_F4 + LAB_F4)// 1312 float4 = 20992 B
#define STAGES 3
#define DYN_BYTES (STAGES * STAGE_F4 * 16)  // 62976 B dynamic smem
#define LOOKAHEAD 2
#define TPB 512
#define G 416                      // 13*32: single wave at 3 blocks/SM on 148 SMs
#define BPB (G / BB)               // 13 blocks per batch (loc partials)

// Scratch (static __device__ — no allocation allowed)
__device__ float g_ce[NPRI];       // per-prior CE
__device__ float g_bg[NPRI];       // per-prior bg loss, -inf on positives
__device__ float g_cepart[G];      // per-block partial CE sum
__device__ float g_sl1part[G];     // per-block smooth-L1 partial
__device__ int   g_nppart[G];      // per-block positive-count partial
__device__ int   g_npos[BB];       // per-batch positive count (finisher-built)
__device__ int   g_ctr;            // finisher counter (zero-init, reset each call)

__device__ __forceinline__ void cp16(uint32_t dst_smem, const void* src) {
    asm volatile("cp.async.cg.shared.global [%0], [%1], 16;" :: "r"(dst_smem), "l"(src));
}
__device__ __forceinline__ void cp_commit() {
    asm volatile("cp.async.commit_group;");
}
template <int N> __device__ __forceinline__ void cp_wait() {
    asm volatile("cp.async.wait_group %0;" :: "n"(N));
}

// ---------------------------------------------------------------------------
// k1: whole problem, one kernel, G=416 persistent blocks of 512 threads
// (single wave, 3 blocks/SM). Tile = 64 rows (21 KB, DYNAMIC smem) -> half
// the barrier/shuffle epochs per byte vs 32-row tiles.
//  1) cp.async prologue: 2 conf tiles in flight
//  2) loc slice (~672 priors/block; slice bounds align with batch bounds)
//  3) conf pipeline: wait<1>/barrier/compute/issue t+2/commit
//  4) last block finalizes; general mining fallback reads bg via L2.
// ---------------------------------------------------------------------------
__global__ void __launch_bounds__(TPB, 3) k1(const float* __restrict__ conf,
                                             const float* __restrict__ pred,
                                             const float* __restrict__ gt,
                                             const int* __restrict__ labels,
                                             float* __restrict__ out) {
    extern __shared__ float4 stg[];            // STAGES * STAGE_F4 float4
    __shared__ float  sred[TPB];
    __shared__ int    sint[TPB];
    __shared__ int    s_last;
    __shared__ int    s_fast;
    __shared__ float  s_cs;
    const int bx   = blockIdx.x;
    const int tid  = threadIdx.x;
    const int lane = tid & 31;
    const int wid  = tid >> 5;
    const unsigned FULL = 0xffffffffu;

    const int start = (int)(((long long)bx * NTILES) / G);
    const int end   = (int)(((long long)(bx + 1) * NTILES) / G);
    const float4* conf4 = reinterpret_cast<const float4*>(conf);
    const int4*   lab4  = reinterpret_cast<const int4*>(labels);

    auto issue = [&](int t, int s) {
        uint32_t sbase = (uint32_t)__cvta_generic_to_shared(&stg[s * STAGE_F4]);
        #pragma unroll
        for (int i = tid; i < STAGE_F4; i += TPB) {   // <= 3 iterations
            const void* src = (i < TILE_F4)
                ? (const void*)(conf4 + (size_t)t * TILE_F4 + i)
                : (const void*)(lab4 + (size_t)t * LAB_F4 + (i - TILE_F4));
            cp16(sbase + (uint32_t)i * 16u, src);
        }
    };

    // ---- 1) prologue: LOOKAHEAD tiles in flight ----
    #pragma unroll
    for (int i = 0; i < LOOKAHEAD; i++) {
        if (start + i < end) issue(start + i, i);
        cp_commit();                       // always commit (group-count invariant)
    }

    // ---- 2) loc slice (overlaps the fills) ----
    {
        const int p0 = (int)(((long long)bx * NPRI) / G);
        const int p1 = (int)(((long long)(bx + 1) * NPRI) / G);
        int   np  = 0;
        float sl1 = 0.f;
        for (int p = p0 + tid; p < p1; p += TPB) {
            const int lab = labels[p];
            if (lab > 0) {
                np++;
                const float4 pv = *reinterpret_cast<const float4*>(pred + (size_t)p * 4);
                const float4 gv = *reinterpret_cast<const float4*>(gt   + (size_t)p * 4);
                float d, ad;
                d = pv.x - gv.x; ad = fabsf(d); sl1 += (ad < 1.f) ? 0.5f * d * d : ad - 0.5f;
                d = pv.y - gv.y; ad = fabsf(d); sl1 += (ad < 1.f) ? 0.5f * d * d : ad - 0.5f;
                d = pv.z - gv.z; ad = fabsf(d); sl1 += (ad < 1.f) ? 0.5f * d * d : ad - 0.5f;
                d = pv.w - gv.w; ad = fabsf(d); sl1 += (ad < 1.f) ? 0.5f * d * d : ad - 0.5f;
            }
        }
        sred[tid] = sl1;
        sint[tid] = np;
        __syncthreads();
        for (int st = TPB / 2; st > 0; st >>= 1) {
            if (tid < st) { sred[tid] += sred[tid + st]; sint[tid] += sint[tid + st]; }
            __syncthreads();
        }
        if (tid == 0) { g_sl1part[bx] = sred[0]; g_nppart[bx] = sint[0]; }
    }

    // ---- 3) conf pipeline ----
    float ce_acc = 0.f;
    const int row = (wid << 2) + (lane >> 3);  // 4 rows per warp, 16 warps = 64 rows
    const int sub = lane & 7;                  // 8 workers per row

    for (int t = start; t < end; t++) {
        const int s = (t - start) % STAGES;
        cp_wait<LOOKAHEAD - 1>();  // groups through tile t complete
        __syncthreads();           // visible block-wide; stage t-1 fully consumed

        const float* sp   = reinterpret_cast<const float*>(&stg[s * STAGE_F4]);
        const int*   slab = reinterpret_cast<const int*>(sp + TILE_FLOATS);
        const float* rp   = sp + row * CC;

        float a0 = 0.f, a1 = 0.f;
        #pragma unroll
        for (int k = 0; k < 10; k += 2) {
            a0 += __expf(rp[sub + 8 * k]);
            a1 += __expf(rp[sub + 8 * (k + 1)]);
        }
        float a = a0 + a1;
        const int lab = slab[row];
        if (sub == 0) a += __expf(rp[80]);
        a += __shfl_xor_sync(FULL, a, 1);
        a += __shfl_xor_sync(FULL, a, 2);
        a += __shfl_xor_sync(FULL, a, 4);
        if (sub == 0) {
            const float lse  = __logf(a);
            const float pick = rp[lab];
            const float x0   = rp[0];
            const float ce   = lse - pick;
            const int   rg   = t * TROWS + row;
            g_ce[rg] = ce;
            g_bg[rg] = (lab > 0) ? -INFINITY : (lse - x0);
            ce_acc += ce;
        }
        // issue tile t+LOOKAHEAD into the stage that held tile t-1
        const int tn = t + LOOKAHEAD;
        if (tn < end) issue(tn, (tn - start) % STAGES);
        cp_commit();               // always commit (keeps wait<1> aligned to tile t)
    }
    cp_wait<0>();

    // per-block CE partial (static tile assignment -> deterministic)
    sred[tid] = ce_acc;
    __syncthreads();
    for (int st = TPB / 2; st > 0; st >>= 1) {
        if (tid < st) sred[tid] += sred[tid + st];
        __syncthreads();
    }
    if (tid == 0) g_cepart[bx] = sred[0];

    // ---- 4) finisher (last block of the grid) ----
    if (tid == 0) {
        __threadfence();
        s_last = (atomicAdd(&g_ctr, 1) == G - 1);
    }
    __syncthreads();
    if (!s_last) return;

    // rebuild per-batch npos: batch b == blocks [13b, 13b+13) exactly
    int slow = 0;
    if (tid < BB) {
        int np = 0;
        #pragma unroll
        for (int i = 0; i < BPB; i++) np += g_nppart[tid * BPB + i];
        g_npos[tid] = np;
        slow = ((long long)np * 3 < (long long)PP);
    }
    const unsigned slowmask = __ballot_sync(FULL, slow);  // warp 0's is meaningful
    if (tid == 0) s_fast = (slowmask == 0u);
    __syncthreads();

    if (s_fast) {
        // total CE = sum of all block partials (fixed order -> deterministic)
        float cs = 0.f;
        for (int i = tid; i < G; i += TPB) cs += g_cepart[i];
        sred[tid] = cs;
        __syncthreads();
        for (int st = TPB / 2; st > 0; st >>= 1) {
            if (tid < st) sred[tid] += sred[tid + st];
            __syncthreads();
        }
        if (tid == 0) s_cs = sred[0];
        __syncthreads();
    } else {
        // general path (correctness fallback; O(P^2) mining, bg via L2)
        if (tid == 0) s_cs = 0.f;
        __syncthreads();
        for (int b = 0; b < BB; b++) {
            const int np = g_npos[b];
            const long long num_neg = (long long)np * 3;
            const float* ce = g_ce + b * PP;
            const float* bg = g_bg + b * PP;
            float acc = 0.f;
            if (num_neg >= PP) {
                for (int p = tid; p < PP; p += TPB) acc += ce[p];
            } else {
                for (int p = tid; p < PP; p += TPB) {
                    const float v = bg[p];
                    bool sel;
                    if (v == -INFINITY) {
                        sel = true;  // positive: always selected
                    } else {
                        int rank = 0;
                        for (int j = 0; j < PP; j++) {
                            const float w = bg[j];
                            rank += (w > v) || (w == v && j < p);  // stable-argsort tiebreak
                        }
                        sel = (rank < num_neg);
                    }
                    if (sel) acc += ce[p];
                }
            }
            sred[tid] = acc;
            __syncthreads();
            for (int st = TPB / 2; st > 0; st >>= 1) {
                if (tid < st) sred[tid] += sred[tid + st];
                __syncthreads();
            }
            if (tid == 0) s_cs += sred[0];  // fixed batch order -> deterministic
            __syncthreads();
        }
    }

    // common tail: total smooth-L1 + total npos, write out[]
    float sl = 0.f;
    for (int i = tid; i < G; i += TPB) sl += g_sl1part[i];
    sred[tid] = sl;
    __syncthreads();
    for (int st = TPB / 2; st > 0; st >>= 1) {
        if (tid < st) sred[tid] += sred[tid + st];
        __syncthreads();
    }
    if (tid < 32) {  // BB == 32
        int np = g_npos[tid];
        #pragma unroll
        for (int o = 16; o > 0; o >>= 1) np += __shfl_xor_sync(FULL, np, o);
        if (tid == 0) {
            const float inv = 1.f / (float)np;
            out[0] = sred[0] * inv;
            out[1] = s_cs * inv;
            g_ctr = 0;   // reset for next replay
        }
    }
}

// ---------------------------------------------------------------------------
extern "C" void kernel_launch(void* const* d_in, const int* in_sizes, int n_in,
                              void* d_out, int out_size) {
    const float* conf   = (const float*)d_in[0];   // (32, 8732, 81) f32
    const float* pred   = (const float*)d_in[1];   // (32, 8732, 4)  f32
    const int*   labels = (const int*)d_in[2];     // (32, 8732)     i32
    const float* gt     = (const float*)d_in[3];   // (32, 8732, 4)  f32
    float* out = (float*)d_out;                    // 2 floats

    // opt-in for >48KB dynamic smem (host attribute set; no allocation,
    // not a stream op -> graph-capture safe, idempotent)
    cudaFuncSetAttribute(k1, cudaFuncAttributeMaxDynamicSharedMemorySize, DYN_BYTES);
    k1<<<G, TPB, DYN_BYTES>>>(conf, pred, gt, labels, out);
}

// round 15
// speedup vs baseline: 1.1416x; 1.0713x over previous
#include <cuda_runtime.h>
#include <math.h>
#include <stdint.h>

// Problem shape (fixed by the reference setup_inputs)
#define BB 32
#define PP 8732
#define CC 81
#define NPRI (BB * PP)             // 279424 rows
#define TROWS 32                   // rows per tile
#define NTILES (NPRI / TROWS)      // 8732 (exact)
#define TILE_FLOATS (TROWS * CC)   // 2592
#define TILE_F4 (TILE_FLOATS / 4)  // 648
#define LAB_F4 (TROWS / 4)         // 8 (labels staged as int4)
#define STAGE_F4 (TILE_F4 + LAB_F4)// 656 float4 = 10496 B
#define STAGES 4                   // 41984 B of stages
#define LOOKAHEAD 3
#define TPB 256
#define G 736                      // 32*23: single wave at 5 blocks/SM on 148 SMs
#define BPB (G / BB)               // 23 blocks per batch (loc partials)

// Scratch (static __device__ — no allocation allowed)
__device__ float g_ce[NPRI];       // per-prior CE
__device__ float g_bg[NPRI];       // per-prior bg loss, -inf on positives
__device__ float g_cepart[G];      // per-block partial CE sum
__device__ float g_sl1part[G];     // per-block smooth-L1 partial
__device__ int   g_nppart[G];      // per-block positive-count partial
__device__ int   g_npos[BB];       // per-batch positive count (finisher-built)
__device__ int   g_ctr;            // finisher counter (zero-init, reset each call)

__device__ __forceinline__ void cp16(uint32_t dst_smem, const void* src) {
    asm volatile("cp.async.cg.shared.global [%0], [%1], 16;" :: "r"(dst_smem), "l"(src));
}
__device__ __forceinline__ void cp_commit() {
    asm volatile("cp.async.commit_group;");
}
template <int N> __device__ __forceinline__ void cp_wait() {
    asm volatile("cp.async.wait_group %0;" :: "n"(N));
}

// ---------------------------------------------------------------------------
// k1: the whole problem in one kernel, G=736 persistent blocks (single wave,
// 5 blocks/SM) — the proven 28.8us geometry; hot loop now uses LDS.64
// (float2) reads, halving LDS issue count.
//  1) cp.async prologue: LOOKAHEAD conf tiles in flight
//  2) loc slice (~380 priors/block; slice bounds align with batch bounds)
//  3) conf pipeline: wait<2> / barrier / compute / issue t+3 / commit
//  4) last block finalizes: fast path (mask == all) sums block partials;
//     general path does exact per-batch hard-negative mining (bg via L2).
// ---------------------------------------------------------------------------
__global__ void __launch_bounds__(TPB) k1(const float* __restrict__ conf,
                                          const float* __restrict__ pred,
                                          const float* __restrict__ gt,
                                          const int* __restrict__ labels,
                                          float* __restrict__ out) {
    __shared__ float4 stg[STAGES][STAGE_F4];   // 41984 B
    __shared__ float  sred[TPB];
    __shared__ int    sint[TPB];
    __shared__ int    s_last;
    __shared__ int    s_fast;
    __shared__ float  s_cs;
    const int bx   = blockIdx.x;
    const int tid  = threadIdx.x;
    const int lane = tid & 31;
    const int wid  = tid >> 5;
    const unsigned FULL = 0xffffffffu;

    const int start = (int)(((long long)bx * NTILES) / G);
    const int end   = (int)(((long long)(bx + 1) * NTILES) / G);
    const float4* conf4 = reinterpret_cast<const float4*>(conf);
    const int4*   lab4  = reinterpret_cast<const int4*>(labels);

    auto issue = [&](int t, int s) {
        uint32_t sbase = (uint32_t)__cvta_generic_to_shared(&stg[s][0]);
        for (int i = tid; i < STAGE_F4; i += TPB) {
            const void* src = (i < TILE_F4)
                ? (const void*)(conf4 + (size_t)t * TILE_F4 + i)
                : (const void*)(lab4 + (size_t)t * LAB_F4 + (i - TILE_F4));
            cp16(sbase + (uint32_t)i * 16u, src);
        }
    };

    // ---- 1) prologue: LOOKAHEAD tiles in flight ----
    #pragma unroll
    for (int i = 0; i < LOOKAHEAD; i++) {
        if (start + i < end) issue(start + i, i);
        cp_commit();                       // always commit (group-count invariant)
    }

    // ---- 2) loc slice (overlaps the fills) ----
    {
        const int p0 = (int)(((long long)bx * NPRI) / G);
        const int p1 = (int)(((long long)(bx + 1) * NPRI) / G);
        int   np  = 0;
        float sl1 = 0.f;
        for (int p = p0 + tid; p < p1; p += TPB) {
            const int lab = labels[p];
            if (lab > 0) {
                np++;
                const float4 pv = *reinterpret_cast<const float4*>(pred + (size_t)p * 4);
                const float4 gv = *reinterpret_cast<const float4*>(gt   + (size_t)p * 4);
                float d, ad;
                d = pv.x - gv.x; ad = fabsf(d); sl1 += (ad < 1.f) ? 0.5f * d * d : ad - 0.5f;
                d = pv.y - gv.y; ad = fabsf(d); sl1 += (ad < 1.f) ? 0.5f * d * d : ad - 0.5f;
                d = pv.z - gv.z; ad = fabsf(d); sl1 += (ad < 1.f) ? 0.5f * d * d : ad - 0.5f;
                d = pv.w - gv.w; ad = fabsf(d); sl1 += (ad < 1.f) ? 0.5f * d * d : ad - 0.5f;
            }
        }
        sred[tid] = sl1;
        sint[tid] = np;
        __syncthreads();
        for (int st = TPB / 2; st > 0; st >>= 1) {
            if (tid < st) { sred[tid] += sred[tid + st]; sint[tid] += sint[tid + st]; }
            __syncthreads();
        }
        if (tid == 0) { g_sl1part[bx] = sred[0]; g_nppart[bx] = sint[0]; }
    }

    // ---- 3) conf pipeline ----
    float ce_acc = 0.f;
    const int row  = (wid << 2) + (lane >> 3);  // 4 rows per warp
    const int sub  = lane & 7;                  // 8 workers per row
    const int rodd = row & 1;                   // odd rows: float2 base at col 1

    for (int t = start; t < end; t++) {
        const int s = (t - start) & (STAGES - 1);
        cp_wait<LOOKAHEAD - 1>();  // groups through tile t complete
        __syncthreads();           // visible block-wide; stage t-1 fully consumed

        const float* sp   = reinterpret_cast<const float*>(&stg[s][0]);
        const int*   slab = reinterpret_cast<const int*>(sp + TILE_FLOATS);
        const float* rp   = sp + row * CC;

        // LDS.64 path: even rows cover cols [0,80) via float2, leftover col 80;
        // odd rows cover cols [1,81) via float2 (base rp+1, 8B-aligned), leftover col 0.
        const float2* rp2 = reinterpret_cast<const float2*>(rp + rodd);
        float a0 = 0.f, a1 = 0.f;
        #pragma unroll
        for (int k = 0; k < 5; k++) {
            const float2 v = rp2[sub + 8 * k];
            a0 += __expf(v.x);
            a1 += __expf(v.y);
        }
        float a = a0 + a1;
        const int lab = slab[row];
        if (sub == 0) a += __expf(rp[rodd ? 0 : 80]);   // the leftover column
        a += __shfl_xor_sync(FULL, a, 1);
        a += __shfl_xor_sync(FULL, a, 2);
        a += __shfl_xor_sync(FULL, a, 4);
        if (sub == 0) {
            const float lse  = __logf(a);
            const float pick = rp[lab];
            const float x0   = rp[0];
            const float ce   = lse - pick;
            const int   rg   = t * TROWS + row;
            g_ce[rg] = ce;
            g_bg[rg] = (lab > 0) ? -INFINITY : (lse - x0);
            ce_acc += ce;
        }
        // issue tile t+LOOKAHEAD into the stage that held tile t-1
        const int tn = t + LOOKAHEAD;
        if (tn < end) issue(tn, (tn - start) & (STAGES - 1));
        cp_commit();               // always commit (keeps wait<2> aligned to tile t)
    }
    cp_wait<0>();

    // per-block CE partial (static tile assignment -> deterministic)
    sred[tid] = ce_acc;
    __syncthreads();
    for (int st = TPB / 2; st > 0; st >>= 1) {
        if (tid < st) sred[tid] += sred[tid + st];
        __syncthreads();
    }
    if (tid == 0) g_cepart[bx] = sred[0];

    // ---- 4) finisher (last block of the grid) ----
    if (tid == 0) {
        __threadfence();
        s_last = (atomicAdd(&g_ctr, 1) == G - 1);
    }
    __syncthreads();
    if (!s_last) return;

    // rebuild per-batch npos: batch b == blocks [23b, 23b+23) exactly
    int slow = 0;
    if (tid < BB) {
        int np = 0;
        #pragma unroll
        for (int i = 0; i < BPB; i++) np += g_nppart[tid * BPB + i];
        g_npos[tid] = np;
        slow = ((long long)np * 3 < (long long)PP);
    }
    const unsigned slowmask = __ballot_sync(FULL, slow);  // warp 0's is meaningful
    if (tid == 0) s_fast = (slowmask == 0u);
    __syncthreads();

    if (s_fast) {
        // total CE = sum of all block partials (fixed order -> deterministic)
        float cs = 0.f;
        for (int i = tid; i < G; i += TPB) cs += g_cepart[i];
        sred[tid] = cs;
        __syncthreads();
        for (int st = TPB / 2; st > 0; st >>= 1) {
            if (tid < st) sred[tid] += sred[tid + st];
            __syncthreads();
        }
        if (tid == 0) s_cs = sred[0];
        __syncthreads();
    } else {
        // general path (correctness fallback; O(P^2) mining, bg via L2)
        if (tid == 0) s_cs = 0.f;
        __syncthreads();
        for (int b = 0; b < BB; b++) {
            const int np = g_npos[b];
            const long long num_neg = (long long)np * 3;
            const float* ce = g_ce + b * PP;
            const float* bg = g_bg + b * PP;
            float acc = 0.f;
            if (num_neg >= PP) {
                for (int p = tid; p < PP; p += TPB) acc += ce[p];
            } else {
                for (int p = tid; p < PP; p += TPB) {
                    const float v = bg[p];
                    bool sel;
                    if (v == -INFINITY) {
                        sel = true;  // positive: always selected
                    } else {
                        int rank = 0;
                        for (int j = 0; j < PP; j++) {
                            const float w = bg[j];
                            rank += (w > v) || (w == v && j < p);  // stable-argsort tiebreak
                        }
                        sel = (rank < num_neg);
                    }
                    if (sel) acc += ce[p];
                }
            }
            sred[tid] = acc;
            __syncthreads();
            for (int st = TPB / 2; st > 0; st >>= 1) {
                if (tid < st) sred[tid] += sred[tid + st];
                __syncthreads();
            }
            if (tid == 0) s_cs += sred[0];  // fixed batch order -> deterministic
            __syncthreads();
        }
    }

    // common tail: total smooth-L1 + total npos, write out[]
    float sl = 0.f;
    for (int i = tid; i < G; i += TPB) sl += g_sl1part[i];
    sred[tid] = sl;
    __syncthreads();
    for (int st = TPB / 2; st > 0; st >>= 1) {
        if (tid < st) sred[tid] += sred[tid + st];
        __syncthreads();
    }
    if (tid < 32) {  // BB == 32
        int np = g_npos[tid];
        #pragma unroll
        for (int o = 16; o > 0; o >>= 1) np += __shfl_xor_sync(FULL, np, o);
        if (tid == 0) {
            const float inv = 1.f / (float)np;
            out[0] = sred[0] * inv;
            out[1] = s_cs * inv;
            g_ctr = 0;   // reset for next replay
        }
    }
}

// ---------------------------------------------------------------------------
extern "C" void kernel_launch(void* const* d_in, const int* in_sizes, int n_in,
                              void* d_out, int out_size) {
    const float* conf   = (const float*)d_in[0];   // (32, 8732, 81) f32
    const float* pred   = (const float*)d_in[1];   // (32, 8732, 4)  f32
    const int*   labels = (const int*)d_in[2];     // (32, 8732)     i32
    const float* gt     = (const float*)d_in[3];   // (32, 8732, 4)  f32
    float* out = (float*)d_out;                    // 2 floats

    k1<<<G, TPB>>>(conf, pred, gt, labels, out);
}